// round 3
// baseline (speedup 1.0000x reference)
#include <cuda_runtime.h>
#include <cuda_fp16.h>
#include <cstdint>
#include <cstddef>

// ---------------------------------------------------------------------------
// AdditiveAttention: B=64, S=2048, ENC_H=DEC_H=ATTN=512
//   enc_proj = enc @ W_enc^T             (HMMA mma.sync fp16, fp32 accum)
//   score    = v . tanh(enc_proj + dec_proj)   (fused epilogue)
//   attn     = softmax(score, axis=S)
//   context  = attn @ enc                (fp32)
// Output layout: context [64*512] then attn_weights [64*2048]
// ---------------------------------------------------------------------------

#define BB 64
#define SS 2048
#define HH 512
#define M_TILE 128
#define NTILES ((BB * SS) / M_TILE)   // 1024

// Small scratch only (no giant static arrays this round)
__device__ __half g_Wh[HH * HH];        // fp16 W_enc (0.5 MB)
__device__ float  g_dec_proj[BB * HH];
__device__ float  g_score[BB * SS];
__device__ float  g_part[BB * 4 * HH];

__device__ __forceinline__ uint32_t smem_u32(const void* p) {
    uint32_t a;
    asm("{ .reg .u64 t; cvta.to.shared.u64 t, %1; cvt.u32.u64 %0, t; }"
        : "=r"(a) : "l"(p));
    return a;
}

__device__ __forceinline__ float tanh_fast(float x) {
    float y;
    asm("tanh.approx.f32 %0, %1;" : "=f"(y) : "f"(x));
    return y;
}

__device__ __forceinline__ uint32_t pack_h2(float a, float b) {
    __half2 h = __floats2half2_rn(a, b);
    return *(uint32_t*)&h;
}

#define LDSM4(r0, r1, r2, r3, addr) \
    asm volatile("ldmatrix.sync.aligned.m8n8.x4.shared.b16 {%0,%1,%2,%3}, [%4];" \
                 : "=r"(r0), "=r"(r1), "=r"(r2), "=r"(r3) : "r"(addr))

#define MMA16816(c0, c1, c2, c3, a0, a1, a2, a3, b0, b1) \
    asm volatile("mma.sync.aligned.m16n8k16.row.col.f32.f16.f16.f32 " \
                 "{%0,%1,%2,%3}, {%4,%5,%6,%7}, {%8,%9}, {%0,%1,%2,%3};" \
                 : "+f"(c0), "+f"(c1), "+f"(c2), "+f"(c3) \
                 : "r"(a0), "r"(a1), "r"(a2), "r"(a3), "r"(b0), "r"(b1))

// ---------------------------------------------------------------------------
// K0a: convert W_enc fp32 -> fp16 (0.5 MB, trivial)
// ---------------------------------------------------------------------------
__global__ void __launch_bounds__(256) k_conv_w(const float* __restrict__ W) {
    size_t gid = (size_t)blockIdx.x * 256 + threadIdx.x;   // 32768 thr * 8 elems
    const float4* in4 = (const float4*)W;
    float4 x = in4[gid * 2 + 0];
    float4 y = in4[gid * 2 + 1];
    uint4 o;
    o.x = pack_h2(x.x, x.y); o.y = pack_h2(x.z, x.w);
    o.z = pack_h2(y.x, y.y); o.w = pack_h2(y.z, y.w);
    ((uint4*)g_Wh)[gid] = o;
}

// K0b: dec_proj[b,a] = sum_k dec[b,k] * W_dec[a,k]  (warp per output)
__global__ void __launch_bounds__(256) k_dec_proj(const float* __restrict__ dec,
                                                  const float* __restrict__ Wd) {
    int out  = blockIdx.x * 8 + (threadIdx.x >> 5);   // 0..32767
    int lane = threadIdx.x & 31;
    int b = out >> 9, a = out & 511;
    const float* w = Wd + (size_t)a * HH;
    const float* d = dec + (size_t)b * HH;
    float s = 0.f;
    #pragma unroll
    for (int k = lane; k < HH; k += 32) s += w[k] * d[k];
    #pragma unroll
    for (int o = 16; o; o >>= 1) s += __shfl_xor_sync(0xFFFFFFFFu, s, o);
    if (lane == 0) g_dec_proj[out] = s;
}

// ---------------------------------------------------------------------------
// K1: 128-row tile: enc_proj via HMMA + fused tanh/dot-v epilogue -> scores
//   SMEM: A 128x512 fp16 swizzled [0,131072)
//         B  64x512 fp16 swizzled [131072,196608)
//         dpv float2[512]          [196608,200704)
//         part float[256]          [200704,201728)
// Swizzle: 16B chunk c of row r stored at r*1024 + ((c ^ (r&7))*16)
// ---------------------------------------------------------------------------
#define SM_A    0
#define SM_B    131072
#define SM_DPV  196608
#define SM_PART 200704
#define SMEM_K1 201728

__global__ void __launch_bounds__(512) k_gemm_score(const float* __restrict__ enc,
                                                    const float* __restrict__ v_in) {
    extern __shared__ char sm[];
    const uint32_t sb = smem_u32(sm);
    const int tid  = threadIdx.x;
    const int lane = tid & 31;
    const int w    = tid >> 5;
    const int mt   = w & 7;         // m16 tile within 128 rows
    const int nsub = w >> 3;        // 0/1: which 32-col half of the 64-col N chunk
    const int m0   = blockIdx.x * M_TILE;
    const int b    = blockIdx.x >> 4;      // 16 tiles per batch row-block

    float2* dpv = (float2*)(sm + SM_DPV);
    dpv[tid] = make_float2(g_dec_proj[b * HH + tid], v_in[tid]);

    // ---- Load A tile (fp32 global -> fp16 swizzled SMEM) ----
    const float4* e4 = (const float4*)(enc + (size_t)m0 * HH);
    #pragma unroll
    for (int it = 0; it < 16; it++) {
        int idx = tid + it * 512;          // 8192 16B-chunks
        int r = idx >> 6, c = idx & 63;
        float4 x = e4[r * 128 + c * 2 + 0];
        float4 y = e4[r * 128 + c * 2 + 1];
        uint4 u;
        u.x = pack_h2(x.x, x.y); u.y = pack_h2(x.z, x.w);
        u.z = pack_h2(y.x, y.y); u.w = pack_h2(y.z, y.w);
        *(uint4*)(sm + SM_A + r * 1024 + ((c ^ (r & 7)) << 4)) = u;
    }

    // Per-lane ldmatrix address parameters
    // A x4: mat m = lane>>3; row-block m&1, k-block m>>1
    const int rA  = mt * 16 + ((lane >> 3) & 1) * 8 + (lane & 7);
    const int kbA = lane >> 4;
    const int sA  = rA & 7;
    const uint32_t baseA = sb + SM_A + rA * 1024;
    // B x4: mat m = lane>>3; k-block m&1, n-tile (m>>1)*8
    const int rBl = (lane >> 4) * 8 + (lane & 7);
    const int kbB = (lane >> 3) & 1;

    const int nr0 = nsub * 32 + rBl;        // n-tiles +0 / +8
    const int nr1 = nsub * 32 + 16 + rBl;   // n-tiles +16 / +24
    const int sB0 = nr0 & 7, sB1 = nr1 & 7;
    const uint32_t baseB0 = sb + SM_B + nr0 * 1024;
    const uint32_t baseB1 = sb + SM_B + nr1 * 1024;

    const uint4* wg = (const uint4*)g_Wh;
    float s0 = 0.f, s1 = 0.f;
    const int g = lane >> 2, tig = lane & 3;

    for (int nc = 0; nc < 8; nc++) {
        __syncthreads();                    // previous B chunk fully consumed
        // ---- Load B chunk: W rows nc*64 .. +63, fp16 swizzled ----
        #pragma unroll
        for (int it = 0; it < 8; it++) {
            int idx = tid + it * 512;       // 4096 16B-chunks
            int r = idx >> 6, c = idx & 63;
            uint4 u = wg[((size_t)(nc * 64 + r)) * 64 + c];
            *(uint4*)(sm + SM_B + r * 1024 + ((c ^ (r & 7)) << 4)) = u;
        }
        __syncthreads();

        float acc[4][4];
        #pragma unroll
        for (int j = 0; j < 4; j++)
            acc[j][0] = acc[j][1] = acc[j][2] = acc[j][3] = 0.f;

        #pragma unroll 8
        for (int k8 = 0; k8 < 64; k8 += 2) {   // 32 k16 steps
            uint32_t a0, a1, a2, a3;
            LDSM4(a0, a1, a2, a3, baseA + (((k8 + kbA) ^ sA) << 4));
            uint32_t b0, b1, b2, b3, b4, b5, b6, b7;
            LDSM4(b0, b1, b2, b3, baseB0 + (((k8 + kbB) ^ sB0) << 4));
            LDSM4(b4, b5, b6, b7, baseB1 + (((k8 + kbB) ^ sB1) << 4));
            MMA16816(acc[0][0], acc[0][1], acc[0][2], acc[0][3], a0, a1, a2, a3, b0, b1);
            MMA16816(acc[1][0], acc[1][1], acc[1][2], acc[1][3], a0, a1, a2, a3, b2, b3);
            MMA16816(acc[2][0], acc[2][1], acc[2][2], acc[2][3], a0, a1, a2, a3, b4, b5);
            MMA16816(acc[3][0], acc[3][1], acc[3][2], acc[3][3], a0, a1, a2, a3, b6, b7);
        }

        // ---- Fused epilogue: score partials ----
        // acc[j]: n-tile col base = nc*64 + nsub*32 + j*8 + 2*tig
        //   c0,c1: row mt*16+g cols +0,+1 ; c2,c3: row mt*16+8+g
        #pragma unroll
        for (int j = 0; j < 4; j++) {
            int col = nc * 64 + nsub * 32 + j * 8 + 2 * tig;
            float2 d0 = dpv[col], d1 = dpv[col + 1];
            s0 += tanh_fast(acc[j][0] + d0.x) * d0.y
                + tanh_fast(acc[j][1] + d1.x) * d1.y;
            s1 += tanh_fast(acc[j][2] + d0.x) * d0.y
                + tanh_fast(acc[j][3] + d1.x) * d1.y;
        }
    }

    // Reduce across the 4 lanes of each quad (cols), then across n-halves
    s0 += __shfl_xor_sync(0xFFFFFFFFu, s0, 1);
    s0 += __shfl_xor_sync(0xFFFFFFFFu, s0, 2);
    s1 += __shfl_xor_sync(0xFFFFFFFFu, s1, 1);
    s1 += __shfl_xor_sync(0xFFFFFFFFu, s1, 2);
    float* part = (float*)(sm + SM_PART);
    __syncthreads();
    if ((lane & 3) == 0) {
        part[nsub * 128 + mt * 16 + g]     = s0;
        part[nsub * 128 + mt * 16 + 8 + g] = s1;
    }
    __syncthreads();
    if (tid < 128) g_score[m0 + tid] = part[tid] + part[128 + tid];
}

// ---------------------------------------------------------------------------
// K2: softmax over S per batch; weights -> d_out[B*H ..]
// ---------------------------------------------------------------------------
__global__ void __launch_bounds__(256) k_softmax(float* __restrict__ out) {
    __shared__ float sv[SS];
    __shared__ float red[8];
    __shared__ float bcast;
    const int b = blockIdx.x, tid = threadIdx.x;
    const int wid = tid >> 5, lane = tid & 31;

    float m = -1e30f;
    for (int i = tid; i < SS; i += 256) {
        float x = g_score[b * SS + i];
        sv[i] = x;
        m = fmaxf(m, x);
    }
    #pragma unroll
    for (int o = 16; o; o >>= 1) m = fmaxf(m, __shfl_xor_sync(0xFFFFFFFFu, m, o));
    if (lane == 0) red[wid] = m;
    __syncthreads();
    if (tid == 0) {
        float mm = red[0];
        #pragma unroll
        for (int i = 1; i < 8; i++) mm = fmaxf(mm, red[i]);
        bcast = mm;
    }
    __syncthreads();
    m = bcast;

    float sum = 0.f;
    for (int i = tid; i < SS; i += 256) {
        float e = __expf(sv[i] - m);
        sv[i] = e;
        sum += e;
    }
    #pragma unroll
    for (int o = 16; o; o >>= 1) sum += __shfl_xor_sync(0xFFFFFFFFu, sum, o);
    __syncthreads();
    if (lane == 0) red[wid] = sum;
    __syncthreads();
    if (tid == 0) {
        float ss = 0.f;
        #pragma unroll
        for (int i = 0; i < 8; i++) ss += red[i];
        bcast = ss;
    }
    __syncthreads();
    const float inv = 1.0f / bcast;
    for (int i = tid; i < SS; i += 256)
        out[BB * HH + b * SS + i] = sv[i] * inv;
}

// ---------------------------------------------------------------------------
// K3a: context partials over 512-length S chunks (fp32 enc, deterministic)
// ---------------------------------------------------------------------------
__global__ void __launch_bounds__(256) k_context(const float* __restrict__ enc,
                                                 const float* __restrict__ out) {
    __shared__ float w[512];
    const int tid = threadIdx.x;
    const int b  = blockIdx.x >> 2;
    const int ch = blockIdx.x & 3;
    const int s0 = ch * 512;
    for (int i = tid; i < 512; i += 256)
        w[i] = out[BB * HH + b * SS + s0 + i];
    __syncthreads();
    const float2* E = (const float2*)(enc + ((size_t)(b * SS + s0)) * HH) + tid;
    float ax = 0.f, ay = 0.f;
    #pragma unroll 4
    for (int s = 0; s < 512; s++) {
        float2 f = E[(size_t)s * 256];
        ax = fmaf(w[s], f.x, ax);
        ay = fmaf(w[s], f.y, ay);
    }
    g_part[(size_t)(b * 4 + ch) * HH + 2 * tid + 0] = ax;
    g_part[(size_t)(b * 4 + ch) * HH + 2 * tid + 1] = ay;
}

// K3b: reduce 4 partials -> context in d_out[0 .. B*H)
__global__ void __launch_bounds__(256) k_ctx_reduce(float* __restrict__ out) {
    const int b = blockIdx.x, tid = threadIdx.x;
    for (int i = tid; i < HH; i += 256) {
        float s = g_part[(size_t)(b * 4 + 0) * HH + i]
                + g_part[(size_t)(b * 4 + 1) * HH + i]
                + g_part[(size_t)(b * 4 + 2) * HH + i]
                + g_part[(size_t)(b * 4 + 3) * HH + i];
        out[b * HH + i] = s;
    }
}

// ---------------------------------------------------------------------------
// Launch
// ---------------------------------------------------------------------------
extern "C" void kernel_launch(void* const* d_in, const int* in_sizes, int n_in,
                              void* d_out, int out_size) {
    const float* enc  = (const float*)d_in[0];   // [64,2048,512]
    const float* dec  = (const float*)d_in[1];   // [64,512]
    const float* Wenc = (const float*)d_in[2];   // [512,512]
    const float* Wdec = (const float*)d_in[3];   // [512,512]
    const float* v    = (const float*)d_in[4];   // [1,512]
    float* out = (float*)d_out;                  // [context | attn_weights]

    cudaFuncSetAttribute(k_gemm_score, cudaFuncAttributeMaxDynamicSharedMemorySize, SMEM_K1);

    k_conv_w<<<128, 256>>>(Wenc);
    k_dec_proj<<<4096, 256>>>(dec, Wdec);
    k_gemm_score<<<NTILES, 512, SMEM_K1>>>(enc, v);
    k_softmax<<<64, 256>>>(out);
    k_context<<<256, 256>>>(enc, out);
    k_ctx_reduce<<<64, 256>>>(out);
}

// round 6
// speedup vs baseline: 1.0100x; 1.0100x over previous
#include <cuda_runtime.h>
#include <cuda_fp16.h>
#include <cstdint>
#include <cstddef>

// ---------------------------------------------------------------------------
// AdditiveAttention: B=64, S=2048, ENC_H=DEC_H=ATTN=512
// HMMA mma.sync path (tcgen05 condemned on this environment).
//   enc_proj = enc @ W_enc^T   -> fused tanh/dot-v -> score
//   attn = softmax(score); context = attn @ enc
// Output: context [64*512] then attn_weights [64*2048]
// ---------------------------------------------------------------------------

#define BB 64
#define SS 2048
#define HH 512
#define M_TILE 128
#define NTILES ((BB * SS) / M_TILE)   // 1024

__device__ __half g_Wh[HH * HH];
__device__ float  g_dec_proj[BB * HH];
__device__ float  g_score[BB * SS];
__device__ float  g_part[BB * 8 * HH];

// ---------------------------------------------------------------------------
// helpers
// ---------------------------------------------------------------------------
__device__ __forceinline__ uint32_t smem_u32(const void* p) {
    uint32_t a;
    asm("{ .reg .u64 t; cvta.to.shared.u64 t, %1; cvt.u32.u64 %0, t; }"
        : "=r"(a) : "l"(p));
    return a;
}
__device__ __forceinline__ float tanh_fast(float x) {
    float y; asm("tanh.approx.f32 %0, %1;" : "=f"(y) : "f"(x)); return y;
}
__device__ __forceinline__ uint32_t pack_h2(float a, float b) {
    __half2 h = __floats2half2_rn(a, b);
    return *(uint32_t*)&h;
}

#define CP_ASYNC16(dst, src) \
    asm volatile("cp.async.cg.shared.global [%0], [%1], 16;" \
                 :: "r"(dst), "l"(src) : "memory")
#define CP_COMMIT() asm volatile("cp.async.commit_group;" ::: "memory")
#define CP_WAIT0()  asm volatile("cp.async.wait_group 0;" ::: "memory")
#define CP_WAIT1()  asm volatile("cp.async.wait_group 1;" ::: "memory")

#define LDSM4(r0, r1, r2, r3, addr) \
    asm volatile("ldmatrix.sync.aligned.m8n8.x4.shared.b16 {%0,%1,%2,%3}, [%4];" \
                 : "=r"(r0), "=r"(r1), "=r"(r2), "=r"(r3) : "r"(addr))

#define MMA16816(c0, c1, c2, c3, a0, a1, a2, a3, b0, b1) \
    asm volatile("mma.sync.aligned.m16n8k16.row.col.f32.f16.f16.f32 " \
                 "{%0,%1,%2,%3}, {%4,%5,%6,%7}, {%8,%9}, {%0,%1,%2,%3};" \
                 : "+f"(c0), "+f"(c1), "+f"(c2), "+f"(c3) \
                 : "r"(a0), "r"(a1), "r"(a2), "r"(a3), "r"(b0), "r"(b1))

// ---------------------------------------------------------------------------
// K0a: W_enc fp32 -> fp16
// ---------------------------------------------------------------------------
__global__ void __launch_bounds__(256) k_conv_w(const float* __restrict__ W) {
    size_t gid = (size_t)blockIdx.x * 256 + threadIdx.x;
    const float4* in4 = (const float4*)W;
    float4 x = in4[gid * 2 + 0];
    float4 y = in4[gid * 2 + 1];
    uint4 o;
    o.x = pack_h2(x.x, x.y); o.y = pack_h2(x.z, x.w);
    o.z = pack_h2(y.x, y.y); o.w = pack_h2(y.z, y.w);
    ((uint4*)g_Wh)[gid] = o;
}

// K0b: dec_proj = dec @ W_dec^T (warp per output; W_dec L2-resident after wave 1)
__global__ void __launch_bounds__(256) k_dec_proj(const float* __restrict__ dec,
                                                  const float* __restrict__ Wd) {
    int out  = blockIdx.x * 8 + (threadIdx.x >> 5);
    int lane = threadIdx.x & 31;
    int b = out >> 9, a = out & 511;
    const float* w = Wd + (size_t)a * HH;
    const float* d = dec + (size_t)b * HH;
    float s = 0.f;
    #pragma unroll
    for (int k = lane; k < HH; k += 32) s += w[k] * d[k];
    #pragma unroll
    for (int o = 16; o; o >>= 1) s += __shfl_xor_sync(0xFFFFFFFFu, s, o);
    if (lane == 0) g_dec_proj[out] = s;
}

// ---------------------------------------------------------------------------
// K1 (HMMA): A resident 128x512 fp16; B streamed in 16 chunks of 32 N-rows,
// cp.async double-buffered. Fused tanh/dot-v epilogue.
// Swizzle: 16B chunk c of row r at r*1024 + ((c ^ (r&7))*16)
// ---------------------------------------------------------------------------
#define SM_A    0          // 128 KB
#define SM_B0   131072     // 32 KB
#define SM_B1   163840     // 32 KB
#define SM_DPV  196608     // 4 KB
#define SM_PART 200704     // 1 KB
#define SMEM_K1 201728

__global__ void __launch_bounds__(512) k_gemm_score(const float* __restrict__ enc,
                                                    const float* __restrict__ v_in) {
    extern __shared__ char sm[];
    const uint32_t sb = smem_u32(sm);
    const int tid  = threadIdx.x;
    const int lane = tid & 31;
    const int w    = tid >> 5;
    const int mt   = w & 7;
    const int nsub = w >> 3;            // 0/1: 16-col half of the 32-col chunk
    const int m0   = blockIdx.x * M_TILE;
    const int b    = blockIdx.x >> 4;

    float2* dpv = (float2*)(sm + SM_DPV);
    dpv[tid] = make_float2(g_dec_proj[b * HH + tid], v_in[tid]);

    const uint4* gB = (const uint4*)g_Wh;

    // prefetch B chunk 0 (rows 0..31, all 512 k) via cp.async
    {
        #pragma unroll
        for (int it = 0; it < 4; it++) {
            int idx = tid + it * 512;
            int r = idx >> 6, c = idx & 63;
            CP_ASYNC16(sb + SM_B0 + r * 1024 + (((c ^ (r & 7))) << 4),
                       gB + (size_t)r * 64 + c);
        }
        CP_COMMIT();
    }

    // A tile: fp32 -> fp16 swizzled SMEM (overlaps B0 prefetch)
    const float4* e4 = (const float4*)(enc + (size_t)m0 * HH);
    #pragma unroll
    for (int it = 0; it < 16; it++) {
        int idx = tid + it * 512;
        int r = idx >> 6, c = idx & 63;
        float4 x = e4[r * 128 + c * 2 + 0];
        float4 y = e4[r * 128 + c * 2 + 1];
        uint4 u;
        u.x = pack_h2(x.x, x.y); u.y = pack_h2(x.z, x.w);
        u.z = pack_h2(y.x, y.y); u.w = pack_h2(y.z, y.w);
        *(uint4*)(sm + SM_A + r * 1024 + ((c ^ (r & 7)) << 4)) = u;
    }

    // ldmatrix lane addressing (verified in R3)
    const int rA  = mt * 16 + ((lane >> 3) & 1) * 8 + (lane & 7);
    const int kbA = lane >> 4;
    const int sA  = rA & 7;
    const uint32_t baseA = sb + SM_A + rA * 1024;
    const int rBl = (lane >> 4) * 8 + (lane & 7);
    const int kbB = (lane >> 3) & 1;
    const int nr  = nsub * 16 + rBl;
    const int sB  = nr & 7;

    float s0 = 0.f, s1 = 0.f;
    const int g = lane >> 2, tig = lane & 3;

    for (int nc = 0; nc < 16; nc++) {
        __syncthreads();                          // prev compute done / A visible
        if (nc + 1 < 16) {
            const uint32_t boff = ((nc + 1) & 1) ? SM_B1 : SM_B0;
            #pragma unroll
            for (int it = 0; it < 4; it++) {
                int idx = tid + it * 512;
                int r = idx >> 6, c = idx & 63;
                CP_ASYNC16(sb + boff + r * 1024 + ((c ^ (r & 7)) << 4),
                           gB + (size_t)((nc + 1) * 32 + r) * 64 + c);
            }
            CP_COMMIT();
            CP_WAIT1();                           // chunk nc complete
        } else {
            CP_WAIT0();
        }
        __syncthreads();

        const uint32_t baseB = sb + ((nc & 1) ? SM_B1 : SM_B0) + nr * 1024;

        float acc[2][4];
        #pragma unroll
        for (int j = 0; j < 2; j++)
            acc[j][0] = acc[j][1] = acc[j][2] = acc[j][3] = 0.f;

        #pragma unroll 8
        for (int k8 = 0; k8 < 64; k8 += 2) {
            uint32_t a0, a1, a2, a3, b0, b1, b2, b3;
            LDSM4(a0, a1, a2, a3, baseA + (((k8 + kbA) ^ sA) << 4));
            LDSM4(b0, b1, b2, b3, baseB + (((k8 + kbB) ^ sB) << 4));
            MMA16816(acc[0][0], acc[0][1], acc[0][2], acc[0][3], a0, a1, a2, a3, b0, b1);
            MMA16816(acc[1][0], acc[1][1], acc[1][2], acc[1][3], a0, a1, a2, a3, b2, b3);
        }

        #pragma unroll
        for (int j = 0; j < 2; j++) {
            int col = nc * 32 + nsub * 16 + j * 8 + 2 * tig;
            float2 d0 = dpv[col], d1 = dpv[col + 1];
            s0 += tanh_fast(acc[j][0] + d0.x) * d0.y
                + tanh_fast(acc[j][1] + d1.x) * d1.y;
            s1 += tanh_fast(acc[j][2] + d0.x) * d0.y
                + tanh_fast(acc[j][3] + d1.x) * d1.y;
        }
    }

    s0 += __shfl_xor_sync(0xFFFFFFFFu, s0, 1);
    s0 += __shfl_xor_sync(0xFFFFFFFFu, s0, 2);
    s1 += __shfl_xor_sync(0xFFFFFFFFu, s1, 1);
    s1 += __shfl_xor_sync(0xFFFFFFFFu, s1, 2);
    float* part = (float*)(sm + SM_PART);
    __syncthreads();
    if ((lane & 3) == 0) {
        part[nsub * 128 + mt * 16 + g]     = s0;
        part[nsub * 128 + mt * 16 + 8 + g] = s1;
    }
    __syncthreads();
    if (tid < 128) g_score[m0 + tid] = part[tid] + part[128 + tid];
}

// ---------------------------------------------------------------------------
// K2: softmax per batch (1024 threads for latency); weights -> d_out[B*H ..]
// ---------------------------------------------------------------------------
__global__ void __launch_bounds__(1024) k_softmax(float* __restrict__ out) {
    __shared__ float sv[SS];
    __shared__ float red[32];
    __shared__ float bcast;
    const int b = blockIdx.x, tid = threadIdx.x;
    const int wid = tid >> 5, lane = tid & 31;

    float m = -1e30f;
    #pragma unroll
    for (int i = tid; i < SS; i += 1024) {
        float x = g_score[b * SS + i];
        sv[i] = x;
        m = fmaxf(m, x);
    }
    #pragma unroll
    for (int o = 16; o; o >>= 1) m = fmaxf(m, __shfl_xor_sync(0xFFFFFFFFu, m, o));
    if (lane == 0) red[wid] = m;
    __syncthreads();
    if (tid == 0) {
        float mm = red[0];
        #pragma unroll
        for (int i = 1; i < 32; i++) mm = fmaxf(mm, red[i]);
        bcast = mm;
    }
    __syncthreads();
    m = bcast;

    float sum = 0.f;
    #pragma unroll
    for (int i = tid; i < SS; i += 1024) {
        float e = __expf(sv[i] - m);
        sv[i] = e;
        sum += e;
    }
    #pragma unroll
    for (int o = 16; o; o >>= 1) sum += __shfl_xor_sync(0xFFFFFFFFu, sum, o);
    __syncthreads();
    if (lane == 0) red[wid] = sum;
    __syncthreads();
    if (tid == 0) {
        float ss = 0.f;
        #pragma unroll
        for (int i = 0; i < 32; i++) ss += red[i];
        bcast = ss;
    }
    __syncthreads();
    const float inv = 1.0f / bcast;
    #pragma unroll
    for (int i = tid; i < SS; i += 1024)
        out[BB * HH + b * SS + i] = sv[i] * inv;
}

// ---------------------------------------------------------------------------
// K3a: context partials, 256-seq chunks, 512 CTAs (deterministic)
// ---------------------------------------------------------------------------
__global__ void __launch_bounds__(256) k_context(const float* __restrict__ enc,
                                                 const float* __restrict__ out) {
    __shared__ float w[256];
    const int tid = threadIdx.x;
    const int b  = blockIdx.x >> 3;
    const int ch = blockIdx.x & 7;
    const int s0 = ch * 256;
    w[tid] = out[BB * HH + b * SS + s0 + tid];
    __syncthreads();
    const float2* E = (const float2*)(enc + ((size_t)(b * SS + s0)) * HH) + tid;
    float ax = 0.f, ay = 0.f;
    #pragma unroll 8
    for (int s = 0; s < 256; s++) {
        float2 f = E[(size_t)s * 256];
        ax = fmaf(w[s], f.x, ax);
        ay = fmaf(w[s], f.y, ay);
    }
    g_part[(size_t)(b * 8 + ch) * HH + 2 * tid + 0] = ax;
    g_part[(size_t)(b * 8 + ch) * HH + 2 * tid + 1] = ay;
}

__global__ void __launch_bounds__(256) k_ctx_reduce(float* __restrict__ out) {
    const int b = blockIdx.x, tid = threadIdx.x;
    for (int i = tid; i < HH; i += 256) {
        float s = 0.f;
        #pragma unroll
        for (int c = 0; c < 8; c++)
            s += g_part[(size_t)(b * 8 + c) * HH + i];
        out[b * HH + i] = s;
    }
}

// ---------------------------------------------------------------------------
// Launch
// ---------------------------------------------------------------------------
extern "C" void kernel_launch(void* const* d_in, const int* in_sizes, int n_in,
                              void* d_out, int out_size) {
    const float* enc  = (const float*)d_in[0];
    const float* dec  = (const float*)d_in[1];
    const float* Wenc = (const float*)d_in[2];
    const float* Wdec = (const float*)d_in[3];
    const float* v    = (const float*)d_in[4];
    float* out = (float*)d_out;

    cudaFuncSetAttribute(k_gemm_score, cudaFuncAttributeMaxDynamicSharedMemorySize, SMEM_K1);

    k_conv_w<<<128, 256>>>(Wenc);
    k_dec_proj<<<4096, 256>>>(dec, Wdec);
    k_gemm_score<<<NTILES, 512, SMEM_K1>>>(enc, v);
    k_softmax<<<64, 1024>>>(out);
    k_context<<<512, 256>>>(enc, out);
    k_ctx_reduce<<<64, 256>>>(out);
}